// round 17
// baseline (speedup 1.0000x reference)
#include <cuda_runtime.h>
#include <math.h>

#define B_ 32
#define T_ 256
#define S_ 512
#define H_ 512
#define G_ 2048   // 4*H
#define NB 128    // 8 groups x 16 blocks, 1 block per SM (uniform)
#define NT 512
#define GSZ 16
#define NGRP 8

// smem floats: [0,8192) scr; [8192,24576) wbuf (2 x 8192);
//              [24576,24640) sml; [24640,25152) smF
#define WBUF 8192
#define SML 24576
#define SMF 24640
#define SMEM_FLOATS 25152

// ---------------- cp.async helpers --------------------------------------------
__device__ __forceinline__ void cp16(void* smem, const void* g) {
    unsigned saddr = (unsigned)__cvta_generic_to_shared(smem);
    asm volatile("cp.async.ca.shared.global [%0], [%1], 16;"
                 :: "r"(saddr), "l"(g));
}
#define CP_COMMIT() asm volatile("cp.async.commit_group;" ::: "memory")
#define CP_WAIT1()  asm volatile("cp.async.wait_group 1;" ::: "memory")
#define CP_WAIT0()  asm volatile("cp.async.wait_group 0;" ::: "memory")

// ---------------- scratch: __device__ globals ---------------------------------
__device__ float g_XG[T_ * B_ * G_];       // layer0 pre-gated input (64 MB)
__device__ float g_X1[T_ * B_ * H_];       // layer0 outputs (16 MB)
__device__ float g_XG1[8 * B_ * 1024];     // lay1 gates 0,1 of XG1, 8-deep ring
__device__ float g_h[2 * B_ * H_];
__device__ float g_c[2 * B_ * H_];
__device__ float g_cat[2 * B_ * 2 * H_];   // [wc | hy]
__device__ float g_target[2 * B_ * H_];
__device__ float g_pm[2 * B_ * 2];
__device__ float g_pz[2 * B_ * 2];
__device__ float g_pwc[2 * B_ * 2 * H_];
__device__ float g_M[T_ * B_];             // layer1 softmax max
__device__ float g_iZ[T_ * B_];            // layer1 1/Z

// ---------------- sync state ---------------------------------------------------
__device__ unsigned g_gcnt[NGRP];
__device__ unsigned g_ggen[NGRP];
__device__ unsigned g_grst[NGRP];
__device__ unsigned g_bcnt[2 * B_];        // per-(layer,b) minisync (monotonic)
__device__ unsigned g_p0c[4];              // lay0 F arrivals: 16 per step
__device__ unsigned g_p1[4];               // layer1 consumption progress

__device__ __forceinline__ unsigned atom_add_acqrel(unsigned* p, unsigned v) {
    unsigned old;
    asm volatile("atom.add.acq_rel.gpu.u32 %0, [%1], %2;"
                 : "=r"(old) : "l"(p), "r"(v) : "memory");
    return old;
}
__device__ __forceinline__ unsigned ld_acq(unsigned* p) {
    unsigned v;
    asm volatile("ld.acquire.gpu.u32 %0, [%1];" : "=r"(v) : "l"(p) : "memory");
    return v;
}
__device__ __forceinline__ void st_rel(unsigned* p, unsigned v) {
    asm volatile("st.release.gpu.u32 [%0], %1;" :: "l"(p), "r"(v) : "memory");
}
__device__ __forceinline__ void gbar(int gid, unsigned target) {
    __syncthreads();
    if (threadIdx.x == 0) {
        unsigned old = atom_add_acqrel(&g_gcnt[gid], 1u);
        if (old == GSZ - 1) {
            g_gcnt[gid] = 0;
            st_rel(&g_ggen[gid], target);
        } else {
            while (ld_acq(&g_ggen[gid]) != target) { }
        }
    }
    __syncthreads();
}

// ---------------- precompute XG = x @ Wi0 + (bi0 + bh0), layer 0 only ---------
__global__ void __launch_bounds__(256) k_pre(const float* __restrict__ Xin,
                                             const float* __restrict__ Wi,
                                             const float* __restrict__ bi,
                                             const float* __restrict__ bh) {
    __shared__ float As[16][128];
    __shared__ float Bs[16][64];
    const int tid = threadIdx.x;
    const int tx = tid & 15, ty = tid >> 4;
    const int n0 = blockIdx.x * 64, m0 = blockIdx.y * 128;
    const int m_l = tid & 127, kb = (tid >> 7) * 8;
    const int m = m0 + m_l;
    const int bb = m & 31, tt = m >> 5;
    const float* arow = Xin + ((size_t)bb * T_ + tt) * H_;
    const int bkk = tid >> 4, bnn = (tid & 15) * 4;

    float acc[8][4];
#pragma unroll
    for (int i = 0; i < 8; i++)
#pragma unroll
        for (int j = 0; j < 4; j++) acc[i][j] = 0.f;

    for (int k0 = 0; k0 < H_; k0 += 16) {
        float4 a0 = *(const float4*)(arow + k0 + kb);
        float4 a1 = *(const float4*)(arow + k0 + kb + 4);
        As[kb + 0][m_l] = a0.x; As[kb + 1][m_l] = a0.y;
        As[kb + 2][m_l] = a0.z; As[kb + 3][m_l] = a0.w;
        As[kb + 4][m_l] = a1.x; As[kb + 5][m_l] = a1.y;
        As[kb + 6][m_l] = a1.z; As[kb + 7][m_l] = a1.w;
        *(float4*)&Bs[bkk][bnn] =
            *(const float4*)(Wi + (size_t)(k0 + bkk) * G_ + n0 + bnn);
        __syncthreads();
#pragma unroll
        for (int kk = 0; kk < 16; kk++) {
            float4 b4  = *(const float4*)&Bs[kk][tx * 4];
            float4 alo = *(const float4*)&As[kk][ty * 8];
            float4 ahi = *(const float4*)&As[kk][ty * 8 + 4];
            float av[8] = {alo.x, alo.y, alo.z, alo.w, ahi.x, ahi.y, ahi.z, ahi.w};
#pragma unroll
            for (int i = 0; i < 8; i++) {
                acc[i][0] = fmaf(av[i], b4.x, acc[i][0]);
                acc[i][1] = fmaf(av[i], b4.y, acc[i][1]);
                acc[i][2] = fmaf(av[i], b4.z, acc[i][2]);
                acc[i][3] = fmaf(av[i], b4.w, acc[i][3]);
            }
        }
        __syncthreads();
    }
    float4 b1 = *(const float4*)(bi + n0 + tx * 4);
    float4 b2 = *(const float4*)(bh + n0 + tx * 4);
    float4 bias = {b1.x + b2.x, b1.y + b2.y, b1.z + b2.z, b1.w + b2.w};
#pragma unroll
    for (int i = 0; i < 8; i++) {
        float4 o = {acc[i][0] + bias.x, acc[i][1] + bias.y,
                    acc[i][2] + bias.z, acc[i][3] + bias.w};
        *(float4*)&g_XG[(size_t)(m0 + ty * 8 + i) * G_ + n0 + tx * 4] = o;
    }
}

// ---------------- persistent wavefront kernel ----------------------------------
__global__ void __launch_bounds__(NT, 1) k_wave(
    const float* __restrict__ ctx,
    const float* __restrict__ Wi,
    const float* __restrict__ bi,
    const float* __restrict__ Wh,
    const float* __restrict__ bh,
    const float* __restrict__ Wain,
    const float* __restrict__ Waout,
    const float* __restrict__ h0,
    const float* __restrict__ c0,
    float* __restrict__ outx,
    float* __restrict__ outh,
    float* __restrict__ outc,
    float* __restrict__ outa)
{
    extern __shared__ float sm[];
    float* scr  = sm;           // 8192-float stage/reduce overlay
    float* wbuf = sm + WBUF;    // 2 x 8192-float weight tile buffers
    float* sml  = sm + SML;     // 64-float small area
    float* smF  = sm + SMF;     // 512-float lay1-local XG1 gates 2,3
    const int blk = blockIdx.x, tid = threadIdx.x;
    const int lane = tid & 31, wrp = tid >> 5;
    const int gid = blk >> 4, gblk = blk & 15;
    const int lay = gid >> 2, oct = gid & 3;
    const int b0g = oct * 8;

    const int bC = b0g + (gblk >> 1), qC = gblk & 1;   // phase C/D mapping
    const int j0A = gblk * 32;                         // phase A/F j-slice
    const int n0E = gblk * 32;                         // phase B/E n-slice

    const float* WiL    = Wi    + (size_t)lay * H_ * G_;
    const float* Wi1    = Wi    + (size_t)H_ * G_;
    const float* biL    = bi    + lay * G_;
    const float* bhL    = bh    + lay * G_;
    const float* bi1    = bi    + G_;
    const float* bh1    = bh    + G_;
    const float* WhL    = Wh    + (size_t)lay * H_ * G_;
    const float* WainL  = Wain  + (size_t)lay * H_ * H_;
    const float* WaoutL = Waout + (size_t)lay * 2 * H_ * H_;

    float* hL   = g_h   + lay * B_ * H_;
    float* cL   = g_c   + lay * B_ * H_;
    float* catL = g_cat + lay * B_ * 2 * H_;
    float* tgtL = g_target + lay * B_ * H_;
    float* pmL  = g_pm  + lay * B_ * 2;
    float* pzL  = g_pz  + lay * B_ * 2;
    float* pwcL = g_pwc + (size_t)lay * B_ * 2 * H_;

    for (int t = 0; t < T_; t++) {
        const unsigned tb = (unsigned)t * 4;

        // ===== lay1 gate + F': gates 2,3 of XG1 (cp.async-tiled, K=512) =====
        if (lay == 1) {
            if (tid == 0) {
                unsigned tgt = 16u * (unsigned)(t + 1);
                while (ld_acq(&g_p0c[oct]) < tgt) { }
            }
            __syncthreads();
            {
                const float4* xsrc = (const float4*)(g_X1 + ((size_t)t * B_ + b0g) * H_);
                for (int i = tid; i < 1024; i += NT)
                    ((float4*)scr)[i] = xsrc[i];
            }
            __syncthreads();
            {
                const int n_loc = tid & 63, ks = tid >> 6;   // 8 splits
                float acc[8];
#pragma unroll
                for (int i = 0; i < 8; i++) acc[i] = 0.f;
                // prefetch tile 0: [64 k][64 n], gates 2,3
                for (int c = tid; c < 1024; c += NT) {
                    int krow = c >> 4, sub = c & 15, g8 = sub >> 3, q = sub & 7;
                    cp16(wbuf + krow * 64 + g8 * 32 + q * 4,
                         WiL + (size_t)krow * G_ + (2 + g8) * H_ + j0A + q * 4);
                }
                CP_COMMIT();
                for (int kt = 0; kt < 8; kt++) {
                    float* cur = wbuf + (kt & 1) * 8192;
                    if (kt < 7) {
                        float* nxt = wbuf + ((kt + 1) & 1) * 8192;
                        for (int c = tid; c < 1024; c += NT) {
                            int krow = c >> 4, sub = c & 15, g8 = sub >> 3, q = sub & 7;
                            cp16(nxt + krow * 64 + g8 * 32 + q * 4,
                                 WiL + (size_t)((kt + 1) * 64 + krow) * G_
                                     + (2 + g8) * H_ + j0A + q * 4);
                        }
                        CP_COMMIT();
                        CP_WAIT1();
                    } else {
                        CP_WAIT0();
                    }
                    __syncthreads();
                    const float* hb0 = scr + kt * 64 + ks * 8;
                    const float* wr = cur + (ks * 8) * 64 + n_loc;
#pragma unroll
                    for (int kk4 = 0; kk4 < 2; kk4++) {
                        float w0 = wr[(kk4 * 4 + 0) * 64];
                        float w1 = wr[(kk4 * 4 + 1) * 64];
                        float w2 = wr[(kk4 * 4 + 2) * 64];
                        float w3 = wr[(kk4 * 4 + 3) * 64];
#pragma unroll
                        for (int b = 0; b < 8; b++) {
                            float4 h4 = *(const float4*)(hb0 + b * 512 + kk4 * 4);
                            acc[b] = fmaf(h4.x, w0, fmaf(h4.y, w1,
                                     fmaf(h4.z, w2, fmaf(h4.w, w3, acc[b]))));
                        }
                    }
                    __syncthreads();
                }
#pragma unroll
                for (int b = 0; b < 8; b++)
                    scr[(ks * 64 + n_loc) * 8 + b] = acc[b];
                __syncthreads();
                {
                    int col = tid & 63, bb = tid >> 6;
                    float v = 0.f;
#pragma unroll
                    for (int s2 = 0; s2 < 8; s2++) v += scr[(s2 * 64 + col) * 8 + bb];
                    int nn = (2 + (col >> 5)) * H_ + j0A + (col & 31);
                    v += biL[nn] + bhL[nn];
                    smF[bb * 64 + col] = v;
                }
            }
            __syncthreads();
        }

        // ===== A: gates = XG + h@Wh (cp.async-tiled K=512), fused LSTM =====
        {
            const float* hp = (t == 0) ? (h0) : hL;
            for (int i = tid; i < 1024; i += NT)
                ((float4*)scr)[i] = ((const float4*)(hp + b0g * H_))[i];
            __syncthreads();
            const int n_loc = tid & 127, ks = tid >> 7;   // 4 splits
            float acc[8];
#pragma unroll
            for (int i = 0; i < 8; i++) acc[i] = 0.f;
            // prefetch tile 0: [64 k][128 n], 4 gates x 32 j
            for (int c = tid; c < 2048; c += NT) {
                int krow = c >> 5, sub = c & 31, g8 = sub >> 3, q = sub & 7;
                cp16(wbuf + krow * 128 + g8 * 32 + q * 4,
                     WhL + (size_t)krow * G_ + g8 * H_ + j0A + q * 4);
            }
            CP_COMMIT();
            for (int kt = 0; kt < 8; kt++) {
                float* cur = wbuf + (kt & 1) * 8192;
                if (kt < 7) {
                    float* nxt = wbuf + ((kt + 1) & 1) * 8192;
                    for (int c = tid; c < 2048; c += NT) {
                        int krow = c >> 5, sub = c & 31, g8 = sub >> 3, q = sub & 7;
                        cp16(nxt + krow * 128 + g8 * 32 + q * 4,
                             WhL + (size_t)((kt + 1) * 64 + krow) * G_
                                 + g8 * H_ + j0A + q * 4);
                    }
                    CP_COMMIT();
                    CP_WAIT1();
                } else {
                    CP_WAIT0();
                }
                __syncthreads();
                const float* hb0 = scr + kt * 64 + ks * 16;
                const float* wr = cur + (ks * 16) * 128 + n_loc;
#pragma unroll
                for (int kk4 = 0; kk4 < 4; kk4++) {
                    float w0 = wr[(kk4 * 4 + 0) * 128];
                    float w1 = wr[(kk4 * 4 + 1) * 128];
                    float w2 = wr[(kk4 * 4 + 2) * 128];
                    float w3 = wr[(kk4 * 4 + 3) * 128];
#pragma unroll
                    for (int b = 0; b < 8; b++) {
                        float4 h4 = *(const float4*)(hb0 + b * 512 + kk4 * 4);
                        acc[b] = fmaf(h4.x, w0, fmaf(h4.y, w1,
                                 fmaf(h4.z, w2, fmaf(h4.w, w3, acc[b]))));
                    }
                }
                __syncthreads();
            }
#pragma unroll
            for (int b = 0; b < 8; b++) scr[(ks * 128 + n_loc) * 8 + b] = acc[b];
            __syncthreads();
            for (int slot = tid; slot < 1024; slot += NT) {
                int bb = slot >> 7, nl = slot & 127;
                int g2 = nl >> 5, j2 = nl & 31;
                float v = scr[nl * 8 + bb] + scr[(128 + nl) * 8 + bb]
                        + scr[(256 + nl) * 8 + bb] + scr[(384 + nl) * 8 + bb];
                if (lay == 0) {
                    v += g_XG[(size_t)(t * B_ + b0g + bb) * G_ + g2 * H_ + j0A + j2];
                } else {
                    if (g2 < 2)
                        v += g_XG1[(size_t)(t & 7) * (B_ * 1024)
                                   + (b0g + bb) * 1024 + g2 * 512 + j0A + j2];
                    else
                        v += smF[bb * 64 + (g2 - 2) * 32 + j2];
                }
                scr[4096 + slot] = v;
            }
            __syncthreads();
            if (tid < 256) {
                int bb = tid >> 5, j2 = tid & 31;
                float gi = scr[4096 + bb * 128 + j2];
                float gf = scr[4096 + bb * 128 + 32 + j2];
                float gg = scr[4096 + bb * 128 + 64 + j2];
                float go = scr[4096 + bb * 128 + 96 + j2];
                int b = b0g + bb, j = j0A + j2;
                float cold = (t == 0) ? c0[b * H_ + j] : cL[b * H_ + j];
                float ig = 1.f / (1.f + expf(-gi));
                float fg = 1.f / (1.f + expf(-gf));
                float g2v = tanhf(gg);
                float og = 1.f / (1.f + expf(-go));
                float cy = fg * cold + ig * g2v;
                float hy = og * tanhf(cy);
                cL[b * H_ + j] = cy;
                catL[b * 2 * H_ + H_ + j] = hy;
            }
        }
        gbar(gid, tb + 1);
        if (lay == 1 && gblk == 0 && tid == 0)
            st_rel(&g_p1[oct], (unsigned)(t + 1));

        // ===== B: target = hy @ Wa_in (direct LDG, small) =====
        {
            for (int i = tid; i < 1024; i += NT) {
                int bb = i >> 7, f = i & 127;
                ((float4*)scr)[i] = ((const float4*)(catL + (b0g + bb) * 1024 + 512))[f];
            }
            __syncthreads();
            const int n_loc = tid & 31, ks = tid >> 5;  // 16 splits x 32 k
            float acc[8];
#pragma unroll
            for (int i = 0; i < 8; i++) acc[i] = 0.f;
            const float* wp = WainL + (size_t)(ks * 32) * H_ + n0E + n_loc;
            const float* hb = scr + ks * 32;
#pragma unroll
            for (int k4 = 0; k4 < 8; k4++) {
                float w0 = wp[(size_t)(k4 * 4 + 0) * H_];
                float w1 = wp[(size_t)(k4 * 4 + 1) * H_];
                float w2 = wp[(size_t)(k4 * 4 + 2) * H_];
                float w3 = wp[(size_t)(k4 * 4 + 3) * H_];
#pragma unroll
                for (int b = 0; b < 8; b++) {
                    float4 h4 = ((const float4*)(hb + b * 512))[k4];
                    acc[b] = fmaf(h4.x, w0, fmaf(h4.y, w1,
                             fmaf(h4.z, w2, fmaf(h4.w, w3, acc[b]))));
                }
            }
            __syncthreads();
#pragma unroll
            for (int b = 0; b < 8; b++) scr[(ks * 32 + n_loc) * 8 + b] = acc[b];
            __syncthreads();
            if (tid < 256) {
                int bb = tid >> 5, nn = tid & 31;
                float v = 0.f;
#pragma unroll
                for (int s2 = 0; s2 < 16; s2++) v += scr[(s2 * 32 + nn) * 8 + bb];
                tgtL[(b0g + bb) * H_ + n0E + nn] = v;
            }
        }
        gbar(gid, tb + 2);

        // ===== C: attention — online softmax, 16 s-rows per warp =====
        {
            const int b = bC, q = qC;
            const int sbase = q * 256;
            const float4* tp = (const float4*)(tgtL + b * H_);
            float4 tg0 = tp[lane],      tg1 = tp[32 + lane];
            float4 tg2 = tp[64 + lane], tg3 = tp[96 + lane];
            float m = -3.4e38f, z = 0.f;
            float4 a0 = {0,0,0,0}, a1 = a0, a2 = a0, a3 = a0;
#pragma unroll 4
            for (int i = 0; i < 16; i++) {
                int s = sbase + wrp * 16 + i;
                const float4* cr = (const float4*)(ctx + ((size_t)s * B_ + b) * H_);
                float4 c0v = cr[lane],      c1v = cr[32 + lane];
                float4 c2v = cr[64 + lane], c3v = cr[96 + lane];
                float p = c0v.x * tg0.x + c0v.y * tg0.y + c0v.z * tg0.z + c0v.w * tg0.w
                        + c1v.x * tg1.x + c1v.y * tg1.y + c1v.z * tg1.z + c1v.w * tg1.w
                        + c2v.x * tg2.x + c2v.y * tg2.y + c2v.z * tg2.z + c2v.w * tg2.w
                        + c3v.x * tg3.x + c3v.y * tg3.y + c3v.z * tg3.z + c3v.w * tg3.w;
#pragma unroll
                for (int o = 16; o; o >>= 1) p += __shfl_xor_sync(0xffffffffu, p, o);
                if (!lane && lay == 1)
                    outa[(size_t)s * (T_ * B_) + t * B_ + b] = p;   // raw score
                float mn = fmaxf(m, p);
                float sc = expf(m - mn);
                float e  = expf(p - mn);
                z = z * sc + e;
                a0.x = a0.x * sc + e * c0v.x; a0.y = a0.y * sc + e * c0v.y;
                a0.z = a0.z * sc + e * c0v.z; a0.w = a0.w * sc + e * c0v.w;
                a1.x = a1.x * sc + e * c1v.x; a1.y = a1.y * sc + e * c1v.y;
                a1.z = a1.z * sc + e * c1v.z; a1.w = a1.w * sc + e * c1v.w;
                a2.x = a2.x * sc + e * c2v.x; a2.y = a2.y * sc + e * c2v.y;
                a2.z = a2.z * sc + e * c2v.z; a2.w = a2.w * sc + e * c2v.w;
                a3.x = a3.x * sc + e * c3v.x; a3.y = a3.y * sc + e * c3v.y;
                a3.z = a3.z * sc + e * c3v.z; a3.w = a3.w * sc + e * c3v.w;
                m = mn;
            }
            if (!lane) { sml[wrp] = m; sml[16 + wrp] = z; }
            __syncthreads();
            if (wrp == 0) {
                float mw = (lane < 16) ? sml[lane] : -3.4e38f;
                float zw = (lane < 16) ? sml[16 + lane] : 0.f;
                float M = mw;
#pragma unroll
                for (int o = 16; o; o >>= 1)
                    M = fmaxf(M, __shfl_xor_sync(0xffffffffu, M, o));
                float cw = expf(mw - M);
                float Zb = zw * cw;
#pragma unroll
                for (int o = 16; o; o >>= 1) Zb += __shfl_xor_sync(0xffffffffu, Zb, o);
                if (lane < 16) sml[32 + lane] = cw;
                if (!lane) { pmL[b * 2 + q] = M; pzL[b * 2 + q] = Zb; }
            }
            __syncthreads();
            float cw = sml[32 + wrp];
            float4* wp4 = (float4*)(scr + wrp * 512);
            float4 s0v = {a0.x*cw, a0.y*cw, a0.z*cw, a0.w*cw};
            float4 s1v = {a1.x*cw, a1.y*cw, a1.z*cw, a1.w*cw};
            float4 s2v = {a2.x*cw, a2.y*cw, a2.z*cw, a2.w*cw};
            float4 s3v = {a3.x*cw, a3.y*cw, a3.z*cw, a3.w*cw};
            wp4[lane] = s0v; wp4[32 + lane] = s1v;
            wp4[64 + lane] = s2v; wp4[96 + lane] = s3v;
            __syncthreads();
            {
                float v = 0.f;
#pragma unroll
                for (int w2 = 0; w2 < 16; w2++) v += scr[w2 * 512 + tid];
                pwcL[((size_t)b * 2 + q) * H_ + tid] = v;
            }
            __syncthreads();
            if (tid == 0) atom_add_acqrel(&g_bcnt[lay * B_ + b], 1u);
        }

        // ===== D: wait 2 partials of (lay,b), combine -> wc =====
        {
            const int b = bC, q = qC;
            const int k0 = q * 256;
            if (tid == 0) {
                unsigned tgt = 2u * (unsigned)(t + 1);
                while (ld_acq(&g_bcnt[lay * B_ + b]) < tgt) { }
            }
            __syncthreads();
            if (wrp == 0) {
                float M2 = (lane < 2) ? pmL[b * 2 + lane] : -3.4e38f;
                float Z2 = (lane < 2) ? pzL[b * 2 + lane] : 0.f;
                float M = M2;
#pragma unroll
                for (int o = 16; o; o >>= 1)
                    M = fmaxf(M, __shfl_xor_sync(0xffffffffu, M, o));
                float cc = expf(M2 - M);
                float Z = Z2 * cc;
#pragma unroll
                for (int o = 16; o; o >>= 1) Z += __shfl_xor_sync(0xffffffffu, Z, o);
                if (lane < 2) sml[lane] = cc;
                if (!lane) {
                    sml[4] = 1.f / Z;
                    if (lay == 1) { g_M[t * B_ + b] = M; g_iZ[t * B_ + b] = 1.f / Z; }
                }
            }
            __syncthreads();
            if (tid < 256) {
                int k = k0 + tid;
                float iZ = sml[4];
                float v = sml[0] * pwcL[((size_t)b * 2 + 0) * H_ + k]
                        + sml[1] * pwcL[((size_t)b * 2 + 1) * H_ + k];
                catL[b * 2 * H_ + k] = v * iZ;
            }
        }
        gbar(gid, tb + 3);

        // ===== E: h = tanh([wc|hy] @ Wa_out) (cp.async-tiled K=1024) =====
        {
            for (int i = tid; i < 2048; i += NT)
                ((float4*)scr)[i] = ((const float4*)(catL + b0g * 1024))[i];
            __syncthreads();
            const int n_loc = tid & 31, ks = tid >> 5;  // 16 splits
            float acc[8];
#pragma unroll
            for (int i = 0; i < 8; i++) acc[i] = 0.f;
            // prefetch tile 0: [128 k][32 n]
            for (int c = tid; c < 1024; c += NT) {
                int krow = c >> 3, q = c & 7;
                cp16(wbuf + krow * 32 + q * 4,
                     WaoutL + (size_t)krow * H_ + n0E + q * 4);
            }
            CP_COMMIT();
            for (int kt = 0; kt < 8; kt++) {
                float* cur = wbuf + (kt & 1) * 8192;
                if (kt < 7) {
                    float* nxt = wbuf + ((kt + 1) & 1) * 8192;
                    for (int c = tid; c < 1024; c += NT) {
                        int krow = c >> 3, q = c & 7;
                        cp16(nxt + krow * 32 + q * 4,
                             WaoutL + (size_t)((kt + 1) * 128 + krow) * H_ + n0E + q * 4);
                    }
                    CP_COMMIT();
                    CP_WAIT1();
                } else {
                    CP_WAIT0();
                }
                __syncthreads();
                const float* hb0 = scr + kt * 128 + ks * 8;
                const float* wr = cur + (ks * 8) * 32 + n_loc;
#pragma unroll
                for (int kk4 = 0; kk4 < 2; kk4++) {
                    float w0 = wr[(kk4 * 4 + 0) * 32];
                    float w1 = wr[(kk4 * 4 + 1) * 32];
                    float w2 = wr[(kk4 * 4 + 2) * 32];
                    float w3 = wr[(kk4 * 4 + 3) * 32];
#pragma unroll
                    for (int b = 0; b < 8; b++) {
                        float4 h4 = *(const float4*)(hb0 + b * 1024 + kk4 * 4);
                        acc[b] = fmaf(h4.x, w0, fmaf(h4.y, w1,
                                 fmaf(h4.z, w2, fmaf(h4.w, w3, acc[b]))));
                    }
                }
                __syncthreads();
            }
#pragma unroll
            for (int b = 0; b < 8; b++) scr[(ks * 32 + n_loc) * 8 + b] = acc[b];
            __syncthreads();
            if (tid < 256) {
                int bb = tid >> 5, nn = tid & 31;
                float v = 0.f;
#pragma unroll
                for (int s2 = 0; s2 < 16; s2++) v += scr[(s2 * 32 + nn) * 8 + bb];
                v = tanhf(v);
                int b = b0g + bb, n = n0E + nn;
                hL[b * H_ + n] = v;
                if (lay == 0)
                    g_X1[((size_t)t * B_ + b) * H_ + n] = v;
                else
                    outx[(size_t)b * (T_ * H_) + (size_t)t * H_ + n] = v;
                if (t == T_ - 1) {
                    outh[lay * B_ * H_ + b * H_ + n] = v;
                    outc[lay * B_ * H_ + b * H_ + n] = cL[b * H_ + n];
                }
            }
        }
        gbar(gid, tb + 4);

        // ===== F (lay0 only): XG1[t] gates 0,1 (cp.async-tiled K=512) =====
        if (lay == 0) {
            if (tid == 0 && t >= 8) {
                unsigned tgt = (unsigned)(t - 7);
                while (ld_acq(&g_p1[oct]) < tgt) { }
            }
            __syncthreads();
            {
                const float4* xsrc = (const float4*)(g_X1 + ((size_t)t * B_ + b0g) * H_);
                for (int i = tid; i < 1024; i += NT)
                    ((float4*)scr)[i] = xsrc[i];
            }
            __syncthreads();
            {
                const int n_loc = tid & 63, ks = tid >> 6;   // 8 splits
                float acc[8];
#pragma unroll
                for (int i = 0; i < 8; i++) acc[i] = 0.f;
                for (int c = tid; c < 1024; c += NT) {
                    int krow = c >> 4, sub = c & 15, g8 = sub >> 3, q = sub & 7;
                    cp16(wbuf + krow * 64 + g8 * 32 + q * 4,
                         Wi1 + (size_t)krow * G_ + g8 * H_ + j0A + q * 4);
                }
                CP_COMMIT();
                for (int kt = 0; kt < 8; kt++) {
                    float* cur = wbuf + (kt & 1) * 8192;
                    if (kt < 7) {
                        float* nxt = wbuf + ((kt + 1) & 1) * 8192;
                        for (int c = tid; c < 1024; c += NT) {
                            int krow = c >> 4, sub = c & 15, g8 = sub >> 3, q = sub & 7;
                            cp16(nxt + krow * 64 + g8 * 32 + q * 4,
                                 Wi1 + (size_t)((kt + 1) * 64 + krow) * G_
                                     + g8 * H_ + j0A + q * 4);
                        }
                        CP_COMMIT();
                        CP_WAIT1();
                    } else {
                        CP_WAIT0();
                    }
                    __syncthreads();
                    const float* hb0 = scr + kt * 64 + ks * 8;
                    const float* wr = cur + (ks * 8) * 64 + n_loc;
#pragma unroll
                    for (int kk4 = 0; kk4 < 2; kk4++) {
                        float w0 = wr[(kk4 * 4 + 0) * 64];
                        float w1 = wr[(kk4 * 4 + 1) * 64];
                        float w2 = wr[(kk4 * 4 + 2) * 64];
                        float w3 = wr[(kk4 * 4 + 3) * 64];
#pragma unroll
                        for (int b = 0; b < 8; b++) {
                            float4 h4 = *(const float4*)(hb0 + b * 512 + kk4 * 4);
                            acc[b] = fmaf(h4.x, w0, fmaf(h4.y, w1,
                                     fmaf(h4.z, w2, fmaf(h4.w, w3, acc[b]))));
                        }
                    }
                    __syncthreads();
                }
#pragma unroll
                for (int b = 0; b < 8; b++)
                    scr[(ks * 64 + n_loc) * 8 + b] = acc[b];
                __syncthreads();
                {
                    int col = tid & 63, bb = tid >> 6;
                    float v = 0.f;
#pragma unroll
                    for (int s2 = 0; s2 < 8; s2++) v += scr[(s2 * 64 + col) * 8 + bb];
                    int g01 = col >> 5, jj = col & 31;
                    int nn = g01 * H_ + j0A + jj;
                    v += bi1[nn] + bh1[nn];
                    g_XG1[(size_t)(t & 7) * (B_ * 1024)
                          + (b0g + bb) * 1024 + g01 * 512 + j0A + jj] = v;
                }
            }
            __syncthreads();
            if (tid == 0) atom_add_acqrel(&g_p0c[oct], 1u);
        }
    }

    // reset sync state for next launch
    if (tid == 0) {
        unsigned old = atom_add_acqrel(&g_grst[gid], 1u);
        if (old == GSZ - 1) {
            g_grst[gid] = 0;
#pragma unroll
            for (int i = 0; i < 8; i++) g_bcnt[lay * B_ + b0g + i] = 0;
            if (lay == 1) { st_rel(&g_p0c[oct], 0u); st_rel(&g_p1[oct], 0u); }
            st_rel(&g_ggen[gid], 0u);
        }
    }
}

// ---------------- finalize attention output: normalize raw scores -------------
__global__ void __launch_bounds__(256) k_att(float* __restrict__ outa) {
    const int s = blockIdx.x;
    for (int i = threadIdx.x; i < T_ * B_; i += 256) {
        float v = outa[(size_t)s * (T_ * B_) + i];
        outa[(size_t)s * (T_ * B_) + i] = expf(v - g_M[i]) * g_iZ[i];
    }
}

// ---------------- host orchestration ------------------------------------------
extern "C" void kernel_launch(void* const* d_in, const int* in_sizes, int n_in,
                              void* d_out, int out_size) {
    const float* input = (const float*)d_in[0];
    const float* h0    = (const float*)d_in[1];
    const float* c0    = (const float*)d_in[2];
    const float* ctx   = (const float*)d_in[3];
    const float* Wi    = (const float*)d_in[4];
    const float* bi    = (const float*)d_in[5];
    const float* Wh    = (const float*)d_in[6];
    const float* bh    = (const float*)d_in[7];
    const float* Wain  = (const float*)d_in[8];
    const float* Waout = (const float*)d_in[9];

    float* out  = (float*)d_out;
    float* outx = out;                                   // (B,T,H)
    float* outh = out  + (size_t)B_ * T_ * H_;           // (2,B,H)
    float* outc = outh + 2 * B_ * H_;                    // (2,B,H)
    float* outa = outc + 2 * B_ * H_;                    // (S, T*B)

    const int SMEM = SMEM_FLOATS * 4;  // 100,608 B -> 1 block/SM
    cudaFuncSetAttribute(k_wave, cudaFuncAttributeMaxDynamicSharedMemorySize, SMEM);

    k_pre<<<dim3(G_ / 64, (T_ * B_) / 128), 256>>>(input, Wi, bi, bh);
    k_wave<<<NB, NT, SMEM>>>(ctx, Wi, bi, Wh, bh, Wain, Waout, h0, c0,
                             outx, outh, outc, outa);
    k_att<<<S_, 256>>>(outa);
}